// round 1
// baseline (speedup 1.0000x reference)
#include <cuda_runtime.h>

#define D_MODEL 1024
#define SEQ     1024
#define BATCH   8
#define NHEAD   16
#define DKH     64
#define NLAYER  2
#define MROWS   (BATCH*SEQ)   // 8192

// 9 scratch buffers of [MROWS, D_MODEL] floats (302 MB, module-load allocated)
__device__ float g_scratch[9ULL * MROWS * D_MODEL];

// ---------------------------------------------------------------------------
// GEMM:  C[m,n] = sum_k X[m,k] * W[n,k]  (+ bias[n]) (+ R[m,n]) (ReLU)
// X: [M,K] row-major, W: [N,K] row-major ([out,in] weights), C: [M,N]
// flags: bit0 = relu, bit1 = residual add
// ---------------------------------------------------------------------------
__global__ __launch_bounds__(256)
void gemm_nt(const float* __restrict__ X, const float* __restrict__ W,
             const float* __restrict__ bias, const float* __restrict__ R,
             float* __restrict__ C, int M, int N, int K, int flags)
{
    __shared__ float Xs[8][128];
    __shared__ float Ws[8][128];
    const int tid = threadIdx.x;
    const int tx = tid & 15, ty = tid >> 4;
    const int bx = blockIdx.x, by = blockIdx.y;
    const int lrow = tid >> 1;
    const int lk   = (tid & 1) << 2;

    const float* Xp = X + (size_t)(by * 128 + lrow) * K + lk;
    const float* Wp = W + (size_t)(bx * 128 + lrow) * K + lk;
    float4 xf = *(const float4*)Xp;
    float4 wf = *(const float4*)Wp;

    float acc[8][8];
#pragma unroll
    for (int i = 0; i < 8; i++)
#pragma unroll
        for (int j = 0; j < 8; j++) acc[i][j] = 0.f;

    const int ktiles = K >> 3;
    for (int t = 0; t < ktiles; t++) {
        Xs[lk + 0][lrow] = xf.x; Xs[lk + 1][lrow] = xf.y;
        Xs[lk + 2][lrow] = xf.z; Xs[lk + 3][lrow] = xf.w;
        Ws[lk + 0][lrow] = wf.x; Ws[lk + 1][lrow] = wf.y;
        Ws[lk + 2][lrow] = wf.z; Ws[lk + 3][lrow] = wf.w;
        __syncthreads();
        if (t + 1 < ktiles) {
            Xp += 8; Wp += 8;
            xf = *(const float4*)Xp;
            wf = *(const float4*)Wp;
        }
#pragma unroll
        for (int kk = 0; kk < 8; kk++) {
            float4 a0 = *(const float4*)&Xs[kk][ty * 4];
            float4 a1 = *(const float4*)&Xs[kk][64 + ty * 4];
            float4 b0 = *(const float4*)&Ws[kk][tx * 4];
            float4 b1 = *(const float4*)&Ws[kk][64 + tx * 4];
            float a[8] = {a0.x, a0.y, a0.z, a0.w, a1.x, a1.y, a1.z, a1.w};
            float bb[8] = {b0.x, b0.y, b0.z, b0.w, b1.x, b1.y, b1.z, b1.w};
#pragma unroll
            for (int i = 0; i < 8; i++)
#pragma unroll
                for (int j = 0; j < 8; j++) acc[i][j] += a[i] * bb[j];
        }
        __syncthreads();
    }

    const bool relu = (flags & 1) != 0;
    const bool res  = (flags & 2) != 0;
    const int cols0 = bx * 128 + tx * 4;
    const int cols1 = bx * 128 + 64 + tx * 4;
    float4 bb0 = *(const float4*)&bias[cols0];
    float4 bb1 = *(const float4*)&bias[cols1];
    float bvals[8] = {bb0.x, bb0.y, bb0.z, bb0.w, bb1.x, bb1.y, bb1.z, bb1.w};

#pragma unroll
    for (int i = 0; i < 8; i++) {
        int r = by * 128 + ((i < 4) ? (ty * 4 + i) : (64 + ty * 4 + (i - 4)));
        size_t base = (size_t)r * N;
#pragma unroll
        for (int jh = 0; jh < 2; jh++) {
            int cc = (jh == 0) ? cols0 : cols1;
            float4 o;
            o.x = acc[i][jh * 4 + 0] + bvals[jh * 4 + 0];
            o.y = acc[i][jh * 4 + 1] + bvals[jh * 4 + 1];
            o.z = acc[i][jh * 4 + 2] + bvals[jh * 4 + 2];
            o.w = acc[i][jh * 4 + 3] + bvals[jh * 4 + 3];
            if (res) {
                float4 rr = *(const float4*)&R[base + cc];
                o.x += rr.x; o.y += rr.y; o.z += rr.z; o.w += rr.w;
            }
            if (relu) {
                o.x = fmaxf(o.x, 0.f); o.y = fmaxf(o.y, 0.f);
                o.z = fmaxf(o.z, 0.f); o.w = fmaxf(o.w, 0.f);
            }
            *(float4*)&C[base + cc] = o;
        }
    }
}

// ---------------------------------------------------------------------------
// Row LayerNorm over D_MODEL=1024, optional fused residual: Y = LN(X (+ Rres))
// ---------------------------------------------------------------------------
__global__ __launch_bounds__(256)
void ln_rows(const float* __restrict__ X, const float* __restrict__ Rres,
             const float* __restrict__ g, const float* __restrict__ b,
             float* __restrict__ Y)
{
    const int row = blockIdx.x;
    const int tid = threadIdx.x;
    const size_t base = (size_t)row * D_MODEL;
    float4 xv = *(const float4*)&X[base + tid * 4];
    if (Rres) {
        float4 rv = *(const float4*)&Rres[base + tid * 4];
        xv.x += rv.x; xv.y += rv.y; xv.z += rv.z; xv.w += rv.w;
    }
    float s  = xv.x + xv.y + xv.z + xv.w;
    float s2 = xv.x * xv.x + xv.y * xv.y + xv.z * xv.z + xv.w * xv.w;
#pragma unroll
    for (int o = 16; o > 0; o >>= 1) {
        s  += __shfl_xor_sync(0xffffffffu, s,  o);
        s2 += __shfl_xor_sync(0xffffffffu, s2, o);
    }
    __shared__ float sh[16];
    int wid = tid >> 5, lane = tid & 31;
    if (lane == 0) { sh[wid] = s; sh[8 + wid] = s2; }
    __syncthreads();
    if (tid == 0) {
        float a = 0.f, c = 0.f;
#pragma unroll
        for (int i = 0; i < 8; i++) { a += sh[i]; c += sh[8 + i]; }
        sh[0] = a; sh[8] = c;
    }
    __syncthreads();
    s = sh[0]; s2 = sh[8];
    float mean = s * (1.f / D_MODEL);
    float var  = s2 * (1.f / D_MODEL) - mean * mean;
    float rstd = rsqrtf(var + 1e-8f);
    float4 gv = *(const float4*)&g[tid * 4];
    float4 bv = *(const float4*)&b[tid * 4];
    float4 y;
    y.x = (xv.x - mean) * rstd * gv.x + bv.x;
    y.y = (xv.y - mean) * rstd * gv.y + bv.y;
    y.z = (xv.z - mean) * rstd * gv.z + bv.z;
    y.w = (xv.w - mean) * rstd * gv.w + bv.w;
    *(float4*)&Y[base + tid * 4] = y;
}

// ---------------------------------------------------------------------------
// Flash attention, fp32. One CTA = (b, h, 64 q-rows). dk = 64, Bk = 64.
// Q/K/V/O in [B,S,H*dk] layout (head h at column offset h*64).
// Scores: clip(s*scale, -30, 30); mask==0 -> -1e9 (the uniform +1e-5 cancels
// in softmax). Online softmax, half-warp (width-16) shuffle reductions.
// ---------------------------------------------------------------------------
__global__ __launch_bounds__(256)
void flash_attn(const float* __restrict__ Qh, const float* __restrict__ Kh,
                const float* __restrict__ Vh, const int* __restrict__ mask,
                float* __restrict__ O)
{
    extern __shared__ float sm[];
    float* Qs = sm;               // [64][68], Qs[d*68 + r]  (transposed)
    float* Ks = sm + 64 * 68;     // [64][68], Ks[d*68 + c]  (transposed)
    float* Vs = sm + 2 * 64 * 68; // [64][68], Vs[k*68 + c]
    float* Ps = sm + 3 * 64 * 68; // [64][68], Ps[r*68 + k]

    const int b  = blockIdx.z, h = blockIdx.y;
    const int q0 = blockIdx.x * 64;
    const int tid = threadIdx.x;
    const int tx = tid & 15, ty = tid >> 4;
    const float scale = 0.125f; // 1/sqrt(64)

    // load Q tile transposed
    {
        int r  = tid >> 2;
        int c0 = (tid & 3) * 16;
        const float* p = Qh + ((size_t)(b * SEQ + q0 + r)) * D_MODEL + h * DKH + c0;
#pragma unroll
        for (int j = 0; j < 16; j += 4) {
            float4 f = *(const float4*)(p + j);
            Qs[(c0 + j + 0) * 68 + r] = f.x;
            Qs[(c0 + j + 1) * 68 + r] = f.y;
            Qs[(c0 + j + 2) * 68 + r] = f.z;
            Qs[(c0 + j + 3) * 68 + r] = f.w;
        }
    }

    float m_i[4], l_i[4], o[4][4];
#pragma unroll
    for (int i = 0; i < 4; i++) {
        m_i[i] = -1e30f; l_i[i] = 0.f;
#pragma unroll
        for (int j = 0; j < 4; j++) o[i][j] = 0.f;
    }
    __syncthreads();

    for (int t = 0; t < SEQ / 64; t++) {
        const int k0 = t * 64;
        // load K (transposed) and V tiles
        {
            int r  = tid >> 2;
            int c0 = (tid & 3) * 16;
            const float* kp = Kh + ((size_t)(b * SEQ + k0 + r)) * D_MODEL + h * DKH + c0;
            const float* vp = Vh + ((size_t)(b * SEQ + k0 + r)) * D_MODEL + h * DKH + c0;
#pragma unroll
            for (int j = 0; j < 16; j += 4) {
                float4 f = *(const float4*)(kp + j);
                Ks[(c0 + j + 0) * 68 + r] = f.x;
                Ks[(c0 + j + 1) * 68 + r] = f.y;
                Ks[(c0 + j + 2) * 68 + r] = f.z;
                Ks[(c0 + j + 3) * 68 + r] = f.w;
                float4 g4 = *(const float4*)(vp + j);
                *(float4*)&Vs[r * 68 + c0 + j] = g4;
            }
        }
        __syncthreads();

        // scores s[4][4]: rows ty*4+i, cols tx*4+j
        float s[4][4];
#pragma unroll
        for (int i = 0; i < 4; i++)
#pragma unroll
            for (int j = 0; j < 4; j++) s[i][j] = 0.f;
#pragma unroll 16
        for (int d = 0; d < 64; d++) {
            float4 a  = *(const float4*)&Qs[d * 68 + ty * 4];
            float4 bb = *(const float4*)&Ks[d * 68 + tx * 4];
            s[0][0] += a.x * bb.x; s[0][1] += a.x * bb.y; s[0][2] += a.x * bb.z; s[0][3] += a.x * bb.w;
            s[1][0] += a.y * bb.x; s[1][1] += a.y * bb.y; s[1][2] += a.y * bb.z; s[1][3] += a.y * bb.w;
            s[2][0] += a.z * bb.x; s[2][1] += a.z * bb.y; s[2][2] += a.z * bb.z; s[2][3] += a.z * bb.w;
            s[3][0] += a.w * bb.x; s[3][1] += a.w * bb.y; s[3][2] += a.w * bb.z; s[3][3] += a.w * bb.w;
        }

        // scale + clip + mask
#pragma unroll
        for (int i = 0; i < 4; i++) {
            const int* mp = mask + ((size_t)(b * SEQ + q0 + ty * 4 + i)) * SEQ + k0 + tx * 4;
            int4 mv = *(const int4*)mp;
            int mm[4] = {mv.x, mv.y, mv.z, mv.w};
#pragma unroll
            for (int j = 0; j < 4; j++) {
                float vv = fminf(fmaxf(s[i][j] * scale, -30.f), 30.f);
                if (mm[j] == 0) vv = -1e9f;
                s[i][j] = vv;
            }
        }

        // online softmax, half-warp reductions (row r = ty*4+i is owned by the
        // 16 threads sharing ty, which are a contiguous half-warp)
#pragma unroll
        for (int i = 0; i < 4; i++) {
            float rm = fmaxf(fmaxf(s[i][0], s[i][1]), fmaxf(s[i][2], s[i][3]));
#pragma unroll
            for (int off = 8; off > 0; off >>= 1)
                rm = fmaxf(rm, __shfl_xor_sync(0xffffffffu, rm, off, 16));
            float mnew  = fmaxf(m_i[i], rm);
            float alpha = __expf(m_i[i] - mnew);
            m_i[i] = mnew;
            float rs = 0.f;
#pragma unroll
            for (int j = 0; j < 4; j++) {
                float p = __expf(s[i][j] - mnew);
                s[i][j] = p; rs += p;
            }
#pragma unroll
            for (int off = 8; off > 0; off >>= 1)
                rs += __shfl_xor_sync(0xffffffffu, rs, off, 16);
            l_i[i] = l_i[i] * alpha + rs;
#pragma unroll
            for (int j = 0; j < 4; j++) o[i][j] *= alpha;
            *(float4*)&Ps[(ty * 4 + i) * 68 + tx * 4] =
                make_float4(s[i][0], s[i][1], s[i][2], s[i][3]);
        }
        __syncthreads();

        // PV: o[i][j] += sum_k Ps[r][k] * Vs[k][c]
#pragma unroll 4
        for (int k4 = 0; k4 < 64; k4 += 4) {
            float4 pr[4], vv[4];
#pragma unroll
            for (int i = 0; i < 4; i++)
                pr[i] = *(const float4*)&Ps[(ty * 4 + i) * 68 + k4];
#pragma unroll
            for (int kk = 0; kk < 4; kk++)
                vv[kk] = *(const float4*)&Vs[(k4 + kk) * 68 + tx * 4];
#pragma unroll
            for (int i = 0; i < 4; i++) {
                float4 p4 = pr[i];
                o[i][0] += p4.x * vv[0].x; o[i][1] += p4.x * vv[0].y;
                o[i][2] += p4.x * vv[0].z; o[i][3] += p4.x * vv[0].w;
                o[i][0] += p4.y * vv[1].x; o[i][1] += p4.y * vv[1].y;
                o[i][2] += p4.y * vv[1].z; o[i][3] += p4.y * vv[1].w;
                o[i][0] += p4.z * vv[2].x; o[i][1] += p4.z * vv[2].y;
                o[i][2] += p4.z * vv[2].z; o[i][3] += p4.z * vv[2].w;
                o[i][0] += p4.w * vv[3].x; o[i][1] += p4.w * vv[3].y;
                o[i][2] += p4.w * vv[3].z; o[i][3] += p4.w * vv[3].w;
            }
        }
        __syncthreads();
    }

#pragma unroll
    for (int i = 0; i < 4; i++) {
        float inv = 1.f / l_i[i];
        float4 yo = make_float4(o[i][0] * inv, o[i][1] * inv,
                                o[i][2] * inv, o[i][3] * inv);
        *(float4*)&O[((size_t)(b * SEQ + q0 + ty * 4 + i)) * D_MODEL + h * DKH + tx * 4] = yo;
    }
}

// ---------------------------------------------------------------------------
extern "C" void kernel_launch(void* const* d_in, const int* in_sizes, int n_in,
                              void* d_out, int out_size)
{
    const float* q    = (const float*)d_in[0];
    const float* k    = (const float*)d_in[1];
    const float* v    = (const float*)d_in[2];
    const int*   mask = (const int*)  d_in[3];
    const float* Wqkv = (const float*)d_in[4];
    const float* bqkv = (const float*)d_in[5];
    const float* Wo   = (const float*)d_in[6];
    const float* bo   = (const float*)d_in[7];
    const float* ln1g = (const float*)d_in[8];
    const float* ln1b = (const float*)d_in[9];
    const float* ln2g = (const float*)d_in[10];
    const float* ln2b = (const float*)d_in[11];
    const float* Wc1  = (const float*)d_in[12];
    const float* bc1  = (const float*)d_in[13];
    const float* Wc2  = (const float*)d_in[14];
    const float* bc2  = (const float*)d_in[15];
    const float* lastg= (const float*)d_in[16];
    const float* lastb= (const float*)d_in[17];
    const float* Wfc  = (const float*)d_in[18];
    const float* bfc  = (const float*)d_in[19];
    float* out = (float*)d_out;

    float* scratch = nullptr;
    cudaGetSymbolAddress((void**)&scratch, g_scratch);
    const size_t BUF = (size_t)MROWS * D_MODEL;
    float* bufQ = scratch + 0 * BUF;
    float* qh   = scratch + 1 * BUF;
    float* kh   = scratch + 2 * BUF;
    float* vh   = scratch + 3 * BUF;
    float* attn = scratch + 4 * BUF;
    float* xb   = scratch + 5 * BUF;
    float* s1   = scratch + 6 * BUF;
    float* s2   = scratch + 7 * BUF;
    float* hb   = scratch + 8 * BUF;

    cudaFuncSetAttribute(flash_attn, cudaFuncAttributeMaxDynamicSharedMemorySize, 69632);

    dim3 gG(D_MODEL / 128, MROWS / 128);
    dim3 gA(SEQ / 64, NHEAD, BATCH);
    const size_t DD = (size_t)D_MODEL * D_MODEL;

    for (int i = 0; i < NLAYER; i++) {
        const float* qs = (i == 0) ? q : s2;
        const float* ks = (i == 0) ? k : s2;
        const float* vs = (i == 0) ? v : s2;

        // Q = LN1(q)
        ln_rows<<<MROWS, 256>>>(qs, nullptr, ln1g + i * D_MODEL, ln1b + i * D_MODEL, bufQ);
        // projections
        gemm_nt<<<gG, 256>>>(bufQ, Wqkv + (size_t)(i * 3 + 0) * DD, bqkv + (i * 3 + 0) * D_MODEL,
                             nullptr, qh, MROWS, D_MODEL, D_MODEL, 0);
        gemm_nt<<<gG, 256>>>(ks,   Wqkv + (size_t)(i * 3 + 1) * DD, bqkv + (i * 3 + 1) * D_MODEL,
                             nullptr, kh, MROWS, D_MODEL, D_MODEL, 0);
        gemm_nt<<<gG, 256>>>(vs,   Wqkv + (size_t)(i * 3 + 2) * DD, bqkv + (i * 3 + 2) * D_MODEL,
                             nullptr, vh, MROWS, D_MODEL, D_MODEL, 0);
        // attention
        flash_attn<<<gA, 256, 69632>>>(qh, kh, vh, mask, attn);
        // x = relu(attn @ Wo^T + bo)
        gemm_nt<<<gG, 256>>>(attn, Wo + (size_t)i * DD, bo + i * D_MODEL,
                             nullptr, xb, MROWS, D_MODEL, D_MODEL, 1);
        // k = LN2(k + x)
        ln_rows<<<MROWS, 256>>>(ks, xb, ln2g + i * D_MODEL, ln2b + i * D_MODEL, s1);
        // FFN: s2 = s1 + (s1 @ Wc1^T + bc1) @ Wc2^T + bc2
        gemm_nt<<<gG, 256>>>(s1, Wc1 + (size_t)i * DD, bc1 + i * D_MODEL,
                             nullptr, hb, MROWS, D_MODEL, D_MODEL, 0);
        gemm_nt<<<gG, 256>>>(hb, Wc2 + (size_t)i * DD, bc2 + i * D_MODEL,
                             s1, s2, MROWS, D_MODEL, D_MODEL, 2);
    }
    // out = LN(s2) @ Wfc^T + bfc
    ln_rows<<<MROWS, 256>>>(s2, nullptr, lastg, lastb, bufQ);
    gemm_nt<<<gG, 256>>>(bufQ, Wfc, bfc, nullptr, out, MROWS, D_MODEL, D_MODEL, 0);
}

// round 15
// speedup vs baseline: 1.7561x; 1.7561x over previous
#include <cuda_runtime.h>
#include <cuda_bf16.h>
#include <cstdint>

#define D_MODEL 1024
#define SEQ     1024
#define BATCH   8
#define NHEAD   16
#define DKH     64
#define NLAYER  2
#define MROWS   (BATCH*SEQ)   // 8192

// 9 scratch buffers of [MROWS, D_MODEL] floats
__device__ float g_scratch[9ULL * MROWS * D_MODEL];

__device__ __forceinline__ uint32_t smem_u32(const void* p) {
    return (uint32_t)__cvta_generic_to_shared(p);
}

// fp32 -> bf16 hi/lo split (packed pairs)
__device__ __forceinline__ void bsplit2(float a, float b, uint32_t& hi, uint32_t& lo) {
    __nv_bfloat162 h = __floats2bfloat162_rn(a, b);
    float ra = a - __bfloat162float(h.x);
    float rb = b - __bfloat162float(h.y);
    __nv_bfloat162 l = __floats2bfloat162_rn(ra, rb);
    hi = *reinterpret_cast<uint32_t*>(&h);
    lo = *reinterpret_cast<uint32_t*>(&l);
}

__device__ __forceinline__ void ldsm4(uint32_t* r, uint32_t addr) {
    asm volatile("ldmatrix.sync.aligned.m8n8.x4.shared.b16 {%0,%1,%2,%3}, [%4];"
                 : "=r"(r[0]), "=r"(r[1]), "=r"(r[2]), "=r"(r[3]) : "r"(addr));
}
__device__ __forceinline__ void ldsm2(uint32_t* r, uint32_t addr) {
    asm volatile("ldmatrix.sync.aligned.m8n8.x2.shared.b16 {%0,%1}, [%2];"
                 : "=r"(r[0]), "=r"(r[1]) : "r"(addr));
}
__device__ __forceinline__ void mma16816(float* d, const uint32_t* a, const uint32_t* b) {
    asm volatile(
        "mma.sync.aligned.m16n8k16.row.col.f32.bf16.bf16.f32 "
        "{%0,%1,%2,%3}, {%4,%5,%6,%7}, {%8,%9}, {%0,%1,%2,%3};"
        : "+f"(d[0]), "+f"(d[1]), "+f"(d[2]), "+f"(d[3])
        : "r"(a[0]), "r"(a[1]), "r"(a[2]), "r"(a[3]), "r"(b[0]), "r"(b[1]));
}

// ===========================================================================
// Tensor-core GEMM via mma.sync (HMMA):
//   C[8192,1024] = X[8192,1024] @ W[1024,1024]^T  (+bias) (+residual) (relu)
// bf16 split: Xhi*Whi + Xhi*Wlo + Xlo*Whi, fp32 accumulators.
// BM=128, BN=128, BK=32, 256 threads (8 warps, 4x2, warp tile 32x64),
// double-buffered SMEM, padded rows (40 bf16 = 80B).
// flags: bit0 = relu, bit1 = residual add
// ===========================================================================
#define PAD    40
#define TILE_E (128 * PAD)          // bf16 elems per tile array
#define GEMM_SMEM (8 * TILE_E * 2)  // 2 bufs * 4 arrays * 10240B = 81920

__global__ void __launch_bounds__(256)
gemm_mma(const float* __restrict__ X, const float* __restrict__ W,
         const float* __restrict__ bias, const float* __restrict__ Rres,
         float* __restrict__ C, int flags)
{
    extern __shared__ __nv_bfloat16 sm[];
    const int tid  = threadIdx.x;
    const int lane = tid & 31;
    const int wid  = tid >> 5;
    const int warp_m = wid >> 1;     // 0..3
    const int warp_n = wid & 1;      // 0..1

    const uint32_t smb = smem_u32(sm);

    float acc[2][8][4];
#pragma unroll
    for (int mi = 0; mi < 2; mi++)
#pragma unroll
        for (int ni = 0; ni < 8; ni++)
#pragma unroll
            for (int j = 0; j < 4; j++) acc[mi][ni][j] = 0.f;

    const int frow = tid >> 3;        // 0..31
    const int fc4  = tid & 7;         // col4 index 0..7
    const float* Xb = X + ((size_t)(blockIdx.y * 128) + frow) * 1024 + fc4 * 4;
    const float* Wb = W + ((size_t)(blockIdx.x * 128) + frow) * 1024 + fc4 * 4;

    // ldmatrix lane address components
    const int aRow    = warp_m * 32 + (lane & 7) + ((lane >> 3) & 1) * 8;
    const int aColSel = (lane >> 4) * 8;
    const int bRow    = warp_n * 64 + (lane & 7);
    const int bColSel = ((lane >> 3) & 1) * 8;

    float4 xr[4], wr[4];
    // prologue: load chunk 0
#pragma unroll
    for (int it = 0; it < 4; it++) {
        xr[it] = *(const float4*)(Xb + (size_t)(it * 32) * 1024);
        wr[it] = *(const float4*)(Wb + (size_t)(it * 32) * 1024);
    }
    // convert+store chunk 0 into buf 0
    {
        __nv_bfloat16* base = sm;  // buf 0
#pragma unroll
        for (int it = 0; it < 4; it++) {
            int row = frow + it * 32;
            uint32_t off = row * PAD + fc4 * 4;   // bf16 index
            uint32_t h0, h1, l0, l1;
            bsplit2(xr[it].x, xr[it].y, h0, l0);
            bsplit2(xr[it].z, xr[it].w, h1, l1);
            *(uint2*)(base + 0 * TILE_E + off) = make_uint2(h0, h1);
            *(uint2*)(base + 1 * TILE_E + off) = make_uint2(l0, l1);
            bsplit2(wr[it].x, wr[it].y, h0, l0);
            bsplit2(wr[it].z, wr[it].w, h1, l1);
            *(uint2*)(base + 2 * TILE_E + off) = make_uint2(h0, h1);
            *(uint2*)(base + 3 * TILE_E + off) = make_uint2(l0, l1);
        }
    }
    __syncthreads();

    for (int ch = 0; ch < 32; ch++) {
        const int buf = ch & 1;
        // issue next chunk's global loads (in flight during mma)
        if (ch + 1 < 32) {
            const float* Xp = Xb + (ch + 1) * 32;
            const float* Wp = Wb + (ch + 1) * 32;
#pragma unroll
            for (int it = 0; it < 4; it++) {
                xr[it] = *(const float4*)(Xp + (size_t)(it * 32) * 1024);
                wr[it] = *(const float4*)(Wp + (size_t)(it * 32) * 1024);
            }
        }

        // compute on buf
        const uint32_t aHi = smb + (uint32_t)(buf * 4 + 0) * TILE_E * 2;
        const uint32_t aLo = smb + (uint32_t)(buf * 4 + 1) * TILE_E * 2;
        const uint32_t bHi = smb + (uint32_t)(buf * 4 + 2) * TILE_E * 2;
        const uint32_t bLo = smb + (uint32_t)(buf * 4 + 3) * TILE_E * 2;
#pragma unroll
        for (int kk = 0; kk < 32; kk += 16) {
            uint32_t ahi[2][4], alo[2][4];
#pragma unroll
            for (int mi = 0; mi < 2; mi++) {
                uint32_t aoff = (uint32_t)((aRow + mi * 16) * PAD + kk + aColSel) * 2;
                ldsm4(ahi[mi], aHi + aoff);
                ldsm4(alo[mi], aLo + aoff);
            }
#pragma unroll
            for (int ni = 0; ni < 8; ni++) {
                uint32_t boff = (uint32_t)((bRow + ni * 8) * PAD + kk + bColSel) * 2;
                uint32_t bhi[2], blo[2];
                ldsm2(bhi, bHi + boff);
                ldsm2(blo, bLo + boff);
#pragma unroll
                for (int mi = 0; mi < 2; mi++) {
                    mma16816(acc[mi][ni], ahi[mi], bhi);
                    mma16816(acc[mi][ni], ahi[mi], blo);
                    mma16816(acc[mi][ni], alo[mi], bhi);
                }
            }
        }

        // convert+store next chunk into other buffer
        if (ch + 1 < 32) {
            __nv_bfloat16* base = sm + (size_t)((buf ^ 1) * 4) * TILE_E;
#pragma unroll
            for (int it = 0; it < 4; it++) {
                int row = frow + it * 32;
                uint32_t off = row * PAD + fc4 * 4;
                uint32_t h0, h1, l0, l1;
                bsplit2(xr[it].x, xr[it].y, h0, l0);
                bsplit2(xr[it].z, xr[it].w, h1, l1);
                *(uint2*)(base + 0 * TILE_E + off) = make_uint2(h0, h1);
                *(uint2*)(base + 1 * TILE_E + off) = make_uint2(l0, l1);
                bsplit2(wr[it].x, wr[it].y, h0, l0);
                bsplit2(wr[it].z, wr[it].w, h1, l1);
                *(uint2*)(base + 2 * TILE_E + off) = make_uint2(h0, h1);
                *(uint2*)(base + 3 * TILE_E + off) = make_uint2(l0, l1);
            }
        }
        __syncthreads();
    }

    // ---- epilogue straight from fragments ----
    const bool relu = (flags & 1) != 0;
    const bool res  = (flags & 2) != 0;
    const int g  = lane >> 2;
    const int t4 = lane & 3;
    const int rbase = blockIdx.y * 128 + warp_m * 32;
    const int cbase = blockIdx.x * 128 + warp_n * 64;
#pragma unroll
    for (int mi = 0; mi < 2; mi++) {
#pragma unroll
        for (int ni = 0; ni < 8; ni++) {
            const int c = cbase + ni * 8 + t4 * 2;
            float2 bb = *(const float2*)&bias[c];
#pragma unroll
            for (int half = 0; half < 2; half++) {
                const int r = rbase + mi * 16 + g + half * 8;
                float2 o;
                o.x = acc[mi][ni][half * 2 + 0] + bb.x;
                o.y = acc[mi][ni][half * 2 + 1] + bb.y;
                const size_t idx = (size_t)r * 1024 + c;
                if (res) {
                    float2 rv = *(const float2*)&Rres[idx];
                    o.x += rv.x; o.y += rv.y;
                }
                if (relu) { o.x = fmaxf(o.x, 0.f); o.y = fmaxf(o.y, 0.f); }
                *(float2*)&C[idx] = o;
            }
        }
    }
}

// ---------------------------------------------------------------------------
// Row LayerNorm over D_MODEL=1024, optional fused residual: Y = LN(X (+ Rres))
// ---------------------------------------------------------------------------
__global__ __launch_bounds__(256)
void ln_rows(const float* __restrict__ X, const float* __restrict__ Rres,
             const float* __restrict__ g, const float* __restrict__ b,
             float* __restrict__ Y)
{
    const int row = blockIdx.x;
    const int tid = threadIdx.x;
    const size_t base = (size_t)row * D_MODEL;
    float4 xv = *(const float4*)&X[base + tid * 4];
    if (Rres) {
        float4 rv = *(const float4*)&Rres[base + tid * 4];
        xv.x += rv.x; xv.y += rv.y; xv.z += rv.z; xv.w += rv.w;
    }
    float s  = xv.x + xv.y + xv.z + xv.w;
    float s2 = xv.x * xv.x + xv.y * xv.y + xv.z * xv.z + xv.w * xv.w;
#pragma unroll
    for (int o = 16; o > 0; o >>= 1) {
        s  += __shfl_xor_sync(0xffffffffu, s,  o);
        s2 += __shfl_xor_sync(0xffffffffu, s2, o);
    }
    __shared__ float sh[16];
    int wid = tid >> 5, lane = tid & 31;
    if (lane == 0) { sh[wid] = s; sh[8 + wid] = s2; }
    __syncthreads();
    if (tid == 0) {
        float a = 0.f, c = 0.f;
#pragma unroll
        for (int i = 0; i < 8; i++) { a += sh[i]; c += sh[8 + i]; }
        sh[0] = a; sh[8] = c;
    }
    __syncthreads();
    s = sh[0]; s2 = sh[8];
    float mean = s * (1.f / D_MODEL);
    float var  = s2 * (1.f / D_MODEL) - mean * mean;
    float rstd = rsqrtf(var + 1e-8f);
    float4 gv = *(const float4*)&g[tid * 4];
    float4 bv = *(const float4*)&b[tid * 4];
    float4 y;
    y.x = (xv.x - mean) * rstd * gv.x + bv.x;
    y.y = (xv.y - mean) * rstd * gv.y + bv.y;
    y.z = (xv.z - mean) * rstd * gv.z + bv.z;
    y.w = (xv.w - mean) * rstd * gv.w + bv.w;
    *(float4*)&Y[base + tid * 4] = y;
}

// ---------------------------------------------------------------------------
// Flash attention, fp32 (measured round 1)
// ---------------------------------------------------------------------------
__global__ __launch_bounds__(256)
void flash_attn(const float* __restrict__ Qh, const float* __restrict__ Kh,
                const float* __restrict__ Vh, const int* __restrict__ mask,
                float* __restrict__ O)
{
    extern __shared__ float smf[];
    float* Qs = smf;               // [64][68] transposed
    float* Ks = smf + 64 * 68;
    float* Vs = smf + 2 * 64 * 68;
    float* Ps = smf + 3 * 64 * 68;

    const int b  = blockIdx.z, h = blockIdx.y;
    const int q0 = blockIdx.x * 64;
    const int tid = threadIdx.x;
    const int tx = tid & 15, ty = tid >> 4;
    const float scale = 0.125f;

    {
        int r  = tid >> 2;
        int c0 = (tid & 3) * 16;
        const float* p = Qh + ((size_t)(b * SEQ + q0 + r)) * D_MODEL + h * DKH + c0;
#pragma unroll
        for (int j = 0; j < 16; j += 4) {
            float4 f = *(const float4*)(p + j);
            Qs[(c0 + j + 0) * 68 + r] = f.x;
            Qs[(c0 + j + 1) * 68 + r] = f.y;
            Qs[(c0 + j + 2) * 68 + r] = f.z;
            Qs[(c0 + j + 3) * 68 + r] = f.w;
        }
    }

    float m_i[4], l_i[4], o[4][4];
#pragma unroll
    for (int i = 0; i < 4; i++) {
        m_i[i] = -1e30f; l_i[i] = 0.f;
#pragma unroll
        for (int j = 0; j < 4; j++) o[i][j] = 0.f;
    }
    __syncthreads();

    for (int t = 0; t < SEQ / 64; t++) {
        const int k0 = t * 64;
        {
            int r  = tid >> 2;
            int c0 = (tid & 3) * 16;
            const float* kp = Kh + ((size_t)(b * SEQ + k0 + r)) * D_MODEL + h * DKH + c0;
            const float* vp = Vh + ((size_t)(b * SEQ + k0 + r)) * D_MODEL + h * DKH + c0;
#pragma unroll
            for (int j = 0; j < 16; j += 4) {
                float4 f = *(const float4*)(kp + j);
                Ks[(c0 + j + 0) * 68 + r] = f.x;
                Ks[(c0 + j + 1) * 68 + r] = f.y;
                Ks[(c0 + j + 2) * 68 + r] = f.z;
                Ks[(c0 + j + 3) * 68 + r] = f.w;
                float4 g4 = *(const float4*)(vp + j);
                *(float4*)&Vs[r * 68 + c0 + j] = g4;
            }
        }
        __syncthreads();

        float s[4][4];
#pragma unroll
        for (int i = 0; i < 4; i++)
#pragma unroll
            for (int j = 0; j < 4; j++) s[i][j] = 0.f;
#pragma unroll 16
        for (int d = 0; d < 64; d++) {
            float4 a  = *(const float4*)&Qs[d * 68 + ty * 4];
            float4 bb = *(const float4*)&Ks[d * 68 + tx * 4];
            s[0][0] += a.x * bb.x; s[0][1] += a.x * bb.y; s[0][2] += a.x * bb.z; s[0][3] += a.x * bb.w;
            s[1][0] += a.y * bb.x; s[1][1] += a.y * bb.y; s[1][2] += a.y * bb.z; s[1][3] += a.y * bb.w;
            s[2][0] += a.z * bb.x; s[2][1] += a.z * bb.y; s[2][2] += a.z * bb.z; s[2][3] += a.z * bb.w;
            s[3][0] += a.w * bb.x; s[3][1] += a.w * bb.y; s[3][2] += a.w * bb.z; s[3][3] += a.w * bb.w;
        }

#pragma unroll
        for (int i = 0; i < 4; i++) {
            const int* mp = mask + ((size_t)(b * SEQ + q0 + ty * 4 + i)) * SEQ + k0 + tx * 4;
            int4 mv = *(const int4*)mp;
            int mm[4] = {mv.x, mv.y, mv.z, mv.w};
#pragma unroll
            for (int j = 0; j < 4; j++) {
                float vv = fminf(fmaxf(s[i][j] * scale, -30.f), 30.f);
                if (mm[j] == 0) vv = -1e9f;
                s[i][j] = vv;
            }
        }

#pragma unroll
        for (int i = 0; i < 4; i++) {
            float rm = fmaxf(fmaxf(s[i][0], s[i][1]), fmaxf(s[i][2], s[i][3]));
#pragma unroll
            for (int off = 8; off > 0; off >>= 1)
                rm = fmaxf(rm, __shfl_xor_sync(0xffffffffu, rm, off, 16));
            float mnew  = fmaxf(m_i[i], rm);
            float alpha = __expf(m_i[i] - mnew);
            m_i[i] = mnew;
            float rs = 0.f;
#pragma unroll
            for (int j = 0; j < 4; j++) {
                float p = __expf(s[i][j] - mnew);
                s[i][j] = p; rs += p;
            }
#pragma unroll
            for (int off = 8; off > 0; off >>= 1)
                rs += __shfl_xor_sync(0xffffffffu, rs, off, 16);
            l_i[i] = l_i[i] * alpha + rs;
#pragma unroll
            for (int j = 0; j < 4; j++) o[i][j] *= alpha;
            *(float4*)&Ps[(ty * 4 + i) * 68 + tx * 4] =
                make_float4(s[i][0], s[i][1], s[i][2], s[i][3]);
        }
        __syncthreads();

#pragma unroll 4
        for (int k4 = 0; k4 < 64; k4 += 4) {
            float4 pr[4], vv[4];
#pragma unroll
            for (int i = 0; i < 4; i++)
                pr[i] = *(const float4*)&Ps[(ty * 4 + i) * 68 + k4];
#pragma unroll
            for (int kk = 0; kk < 4; kk++)
                vv[kk] = *(const float4*)&Vs[(k4 + kk) * 68 + tx * 4];
#pragma unroll
            for (int i = 0; i < 4; i++) {
                float4 p4 = pr[i];
                o[i][0] += p4.x * vv[0].x; o[i][1] += p4.x * vv[0].y;
                o[i][2] += p4.x * vv[0].z; o[i][3] += p4.x * vv[0].w;
                o[i][0] += p4.y * vv[1].x; o[i][1] += p4.y * vv[1].y;
                o[i][2] += p4.y * vv[1].z; o[i][3] += p4.y * vv[1].w;
                o[i][0] += p4.z * vv[2].x; o[i][1] += p4.z * vv[2].y;
                o[i][2] += p4.z * vv[2].z; o[i][3] += p4.z * vv[2].w;
                o[i][0] += p4.w * vv[3].x; o[i][1] += p4.w * vv[3].y;
                o[i][2] += p4.w * vv[3].z; o[i][3] += p4.w * vv[3].w;
            }
        }
        __syncthreads();
    }

#pragma unroll
    for (int i = 0; i < 4; i++) {
        float inv = 1.f / l_i[i];
        float4 yo = make_float4(o[i][0] * inv, o[i][1] * inv,
                                o[i][2] * inv, o[i][3] * inv);
        *(float4*)&O[((size_t)(b * SEQ + q0 + ty * 4 + i)) * D_MODEL + h * DKH + tx * 4] = yo;
    }
}

// ---------------------------------------------------------------------------
extern "C" void kernel_launch(void* const* d_in, const int* in_sizes, int n_in,
                              void* d_out, int out_size)
{
    const float* q    = (const float*)d_in[0];
    const float* k    = (const float*)d_in[1];
    const float* v    = (const float*)d_in[2];
    const int*   mask = (const int*)  d_in[3];
    const float* Wqkv = (const float*)d_in[4];
    const float* bqkv = (const float*)d_in[5];
    const float* Wo   = (const float*)d_in[6];
    const float* bo   = (const float*)d_in[7];
    const float* ln1g = (const float*)d_in[8];
    const float* ln1b = (const float*)d_in[9];
    const float* ln2g = (const float*)d_in[10];
    const float* ln2b = (const float*)d_in[11];
    const float* Wc1  = (const float*)d_in[12];
    const float* bc1  = (const float*)d_in[13];
    const float* Wc2  = (const float*)d_in[14];
    const float* bc2  = (const float*)d_in[15];
    const float* lastg= (const float*)d_in[16];
    const float* lastb= (const float*)d_in[17];
    const float* Wfc  = (const float*)d_in[18];
    const float* bfc  = (const float*)d_in[19];
    float* out = (float*)d_out;

    float* scratch = nullptr;
    cudaGetSymbolAddress((void**)&scratch, g_scratch);
    const size_t BUF = (size_t)MROWS * D_MODEL;
    float* bufQ = scratch + 0 * BUF;
    float* qh   = scratch + 1 * BUF;
    float* kh   = scratch + 2 * BUF;
    float* vh   = scratch + 3 * BUF;
    float* attn = scratch + 4 * BUF;
    float* xb   = scratch + 5 * BUF;
    float* s1   = scratch + 6 * BUF;
    float* s2   = scratch + 7 * BUF;
    float* hb   = scratch + 8 * BUF;

    cudaFuncSetAttribute(flash_attn, cudaFuncAttributeMaxDynamicSharedMemorySize, 69632);
    cudaFuncSetAttribute(gemm_mma,   cudaFuncAttributeMaxDynamicSharedMemorySize, GEMM_SMEM);

    dim3 gG(D_MODEL / 128, MROWS / 128);   // (8, 64)
    dim3 gA(SEQ / 64, NHEAD, BATCH);
    const size_t DD = (size_t)D_MODEL * D_MODEL;

    for (int i = 0; i < NLAYER; i++) {
        const float* qs = (i == 0) ? q : s2;
        const float* ks = (i == 0) ? k : s2;
        const float* vs = (i == 0) ? v : s2;

        // Q = LN1(q)
        ln_rows<<<MROWS, 256>>>(qs, nullptr, ln1g + i * D_MODEL, ln1b + i * D_MODEL, bufQ);
        // projections
        gemm_mma<<<gG, 256, GEMM_SMEM>>>(bufQ, Wqkv + (size_t)(i * 3 + 0) * DD,
                                         bqkv + (i * 3 + 0) * D_MODEL, s1, qh, 0);
        gemm_mma<<<gG, 256, GEMM_SMEM>>>(ks,   Wqkv + (size_t)(i * 3 + 1) * DD,
                                         bqkv + (i * 3 + 1) * D_MODEL, s1, kh, 0);
        gemm_mma<<<gG, 256, GEMM_SMEM>>>(vs,   Wqkv + (size_t)(i * 3 + 2) * DD,
                                         bqkv + (i * 3 + 2) * D_MODEL, s1, vh, 0);
        // attention
        flash_attn<<<gA, 256, 69632>>>(qh, kh, vh, mask, attn);
        // x = relu(attn @ Wo^T + bo)
        gemm_mma<<<gG, 256, GEMM_SMEM>>>(attn, Wo + (size_t)i * DD, bo + i * D_MODEL,
                                         s1, xb, 1);
        // k = LN2(k + x)
        ln_rows<<<MROWS, 256>>>(ks, xb, ln2g + i * D_MODEL, ln2b + i * D_MODEL, s1);
        // FFN: s2 = s1 + (s1 @ Wc1^T + bc1) @ Wc2^T + bc2
        gemm_mma<<<gG, 256, GEMM_SMEM>>>(s1, Wc1 + (size_t)i * DD, bc1 + i * D_MODEL,
                                         s1, hb, 0);
        gemm_mma<<<gG, 256, GEMM_SMEM>>>(hb, Wc2 + (size_t)i * DD, bc2 + i * D_MODEL,
                                         s1, s2, 2);
    }
    // out = LN(s2) @ Wfc^T + bfc
    ln_rows<<<MROWS, 256>>>(s2, nullptr, lastg, lastb, bufQ);
    gemm_mma<<<gG, 256, GEMM_SMEM>>>(bufQ, Wfc, bfc, s1, out, 0);
}